// round 1
// baseline (speedup 1.0000x reference)
#include <cuda_runtime.h>

// VocabularyProjectionFFN: flash-attention formulation.
// Q = (x_head @ W_ffn^T + b) / clamp(temp, 0.1)   (512x64 per head)
// K = W_vocab[h]   (32000x64)
// V = E[:, h*64:(h+1)*64]  (32000x64)
// out = softmax(Q K^T) @ V
//
// Grid: (8 q-tiles of 64 tokens, 12 heads). 256 threads/CTA, KV tile = 128.
// GEMMs via mma.sync m16n8k8 tf32 (fp32 accumulate).

#define QT 64
#define KT 128
#define D_DIM 64
#define V_SZ 32000
#define C_DIM 768

#define SQ_ST 68
#define SK_ST 68
#define SE_ST 68
#define SP_ST 132

#define SMEM_FLOATS (QT*SQ_ST + KT*SK_ST + KT*SE_ST + QT*SP_ST + 3*QT)
#define SMEM_BYTES (SMEM_FLOATS * 4)

__device__ __forceinline__ unsigned f2tf32(float x) {
    unsigned r;
    asm("cvt.rna.tf32.f32 %0, %1;" : "=r"(r) : "f"(x));
    return r;
}

__device__ __forceinline__ void mma_tf32(float* c,
    unsigned a0, unsigned a1, unsigned a2, unsigned a3,
    unsigned b0, unsigned b1)
{
    asm volatile(
        "mma.sync.aligned.m16n8k8.row.col.f32.tf32.tf32.f32 "
        "{%0,%1,%2,%3}, {%4,%5,%6,%7}, {%8,%9}, {%0,%1,%2,%3};"
        : "+f"(c[0]), "+f"(c[1]), "+f"(c[2]), "+f"(c[3])
        : "r"(a0), "r"(a1), "r"(a2), "r"(a3), "r"(b0), "r"(b1));
}

extern "C" __global__ void __launch_bounds__(256)
vpf_kernel(const float* __restrict__ x,
           const float* __restrict__ Wf,
           const float* __restrict__ bfn,
           const float* __restrict__ Wv,
           const float* __restrict__ temps,
           const float* __restrict__ E,
           float* __restrict__ out)
{
    extern __shared__ float sm[];
    float* sQ  = sm;                 // QT x SQ_ST  (tf32-rounded Q, temp-scaled)
    float* sK  = sQ + QT*SQ_ST;      // KT x SK_ST  (K tile; also X tile in prologue)
    float* sE  = sK + KT*SK_ST;      // KT x SE_ST  (E tile; also W_ffn in prologue)
    float* sP  = sE + KT*SE_ST;      // QT x SP_ST  (S then P)
    float* sMx = sP + QT*SP_ST;      // QT running max
    float* sL  = sMx + QT;           // QT running sum
    float* sF  = sL + QT;            // QT rescale factor

    const int h    = blockIdx.y;
    const int qt   = blockIdx.x;
    const int tid  = threadIdx.x;
    const int warp = tid >> 5;
    const int lane = tid & 31;
    const int g    = lane >> 2;      // groupID
    const int tq   = lane & 3;       // threadID_in_group
    const int wm   = warp & 3;       // M-block (rows wm*16..wm*16+15)
    const int wn   = warp >> 2;      // N-half

    float tmp = temps[h];
    const float inv_temp = 1.0f / fmaxf(tmp, 0.1f);

    // ---- prologue: stage X tile -> sK, W_ffn[h] -> sE ----
    for (int it = tid; it < QT*16; it += 256) {
        int i = it >> 4, c4 = (it & 15) << 2;
        float4 v = *(const float4*)(x + (size_t)(qt*QT + i)*C_DIM + h*D_DIM + c4);
        *(float4*)(sK + i*SK_ST + c4) = v;
    }
    for (int it = tid; it < D_DIM*16; it += 256) {
        int e = it >> 4, c4 = (it & 15) << 2;
        float4 v = *(const float4*)(Wf + ((size_t)h*D_DIM + e)*D_DIM + c4);
        *(float4*)(sE + e*SE_ST + c4) = v;
    }
    __syncthreads();

    // Q[i][e] = (sum_d X[i][d]*Wf[e][d] + b[e]) * inv_temp, tf32-rounded
    {
        int i = tid >> 2, q = tid & 3;
        for (int j = 0; j < 16; j++) {
            int e = q + (j << 2);
            float acc = bfn[h*D_DIM + e];
            #pragma unroll
            for (int d = 0; d < D_DIM; d++)
                acc = fmaf(sK[i*SK_ST + d], sE[e*SE_ST + d], acc);
            sQ[i*SQ_ST + e] = __uint_as_float(f2tf32(acc * inv_temp));
        }
    }
    if (tid < QT) { sMx[tid] = -INFINITY; sL[tid] = 0.f; }

    float o[4][4];
    #pragma unroll
    for (int j = 0; j < 4; j++) { o[j][0]=0.f; o[j][1]=0.f; o[j][2]=0.f; o[j][3]=0.f; }

    const float* Kg = Wv + (size_t)h * V_SZ * D_DIM;

    for (int t0 = 0; t0 < V_SZ; t0 += KT) {
        __syncthreads();   // prior phase done with sK/sE (and prologue on iter 0)

        // ---- load K tile + E tile (fp32, float4) ----
        for (int it = tid; it < KT*16; it += 256) {
            int vi = it >> 4, c4 = (it & 15) << 2;
            float4 v = *(const float4*)(Kg + (size_t)(t0+vi)*D_DIM + c4);
            *(float4*)(sK + vi*SK_ST + c4) = v;
        }
        for (int it = tid; it < KT*16; it += 256) {
            int vi = it >> 4, c4 = (it & 15) << 2;
            float4 v = *(const float4*)(E + (size_t)(t0+vi)*C_DIM + h*D_DIM + c4);
            *(float4*)(sE + vi*SE_ST + c4) = v;
        }
        __syncthreads();

        // ---- S = Q K^T  (64x128) ----
        float sacc[8][4];
        #pragma unroll
        for (int j = 0; j < 8; j++) { sacc[j][0]=0.f; sacc[j][1]=0.f; sacc[j][2]=0.f; sacc[j][3]=0.f; }
        #pragma unroll
        for (int ks = 0; ks < 8; ks++) {
            int k0 = ks << 3;
            unsigned a0 = __float_as_uint(sQ[(wm*16+g  )*SQ_ST + k0+tq  ]);
            unsigned a1 = __float_as_uint(sQ[(wm*16+g+8)*SQ_ST + k0+tq  ]);
            unsigned a2 = __float_as_uint(sQ[(wm*16+g  )*SQ_ST + k0+tq+4]);
            unsigned a3 = __float_as_uint(sQ[(wm*16+g+8)*SQ_ST + k0+tq+4]);
            #pragma unroll
            for (int j = 0; j < 8; j++) {
                int n0 = wn*64 + (j << 3);
                unsigned b0 = __float_as_uint(sK[(n0+g)*SK_ST + k0+tq  ]);
                unsigned b1 = __float_as_uint(sK[(n0+g)*SK_ST + k0+tq+4]);
                mma_tf32(sacc[j], a0,a1,a2,a3, b0,b1);
            }
        }
        #pragma unroll
        for (int j = 0; j < 8; j++) {
            int n0 = wn*64 + (j << 3) + 2*tq;
            sP[(wm*16+g  )*SP_ST + n0  ] = sacc[j][0];
            sP[(wm*16+g  )*SP_ST + n0+1] = sacc[j][1];
            sP[(wm*16+g+8)*SP_ST + n0  ] = sacc[j][2];
            sP[(wm*16+g+8)*SP_ST + n0+1] = sacc[j][3];
        }
        __syncthreads();

        // ---- online softmax over this tile (row = tid/4, 4 lanes per row) ----
        {
            int row = tid >> 2, q = tid & 3;
            float* rowp = sP + row*SP_ST;
            float lm = -INFINITY;
            #pragma unroll
            for (int j = 0; j < 32; j++) lm = fmaxf(lm, rowp[q + (j << 2)]);
            lm = fmaxf(lm, __shfl_xor_sync(0xffffffffu, lm, 1));
            lm = fmaxf(lm, __shfl_xor_sync(0xffffffffu, lm, 2));
            float m_old = sMx[row];
            float m_new = fmaxf(m_old, lm);
            float lsum = 0.f;
            #pragma unroll
            for (int j = 0; j < 32; j++) {
                int c = q + (j << 2);
                float p = __expf(rowp[c] - m_new);
                p = __uint_as_float(f2tf32(p));
                rowp[c] = p;
                lsum += p;
            }
            lsum += __shfl_xor_sync(0xffffffffu, lsum, 1);
            lsum += __shfl_xor_sync(0xffffffffu, lsum, 2);
            if (q == 0) {
                float fac = __expf(m_old - m_new);
                sF[row]  = fac;
                sL[row]  = sL[row]*fac + lsum;
                sMx[row] = m_new;
            }
        }
        __syncthreads();

        // ---- rescale O, then O += P @ E_tile  (64x64, K=128) ----
        {
            float f0 = sF[wm*16 + g];
            float f1 = sF[wm*16 + g + 8];
            #pragma unroll
            for (int j = 0; j < 4; j++) { o[j][0]*=f0; o[j][1]*=f0; o[j][2]*=f1; o[j][3]*=f1; }
            #pragma unroll
            for (int ks = 0; ks < 16; ks++) {
                int k0 = ks << 3;
                unsigned a0 = __float_as_uint(sP[(wm*16+g  )*SP_ST + k0+tq  ]);
                unsigned a1 = __float_as_uint(sP[(wm*16+g+8)*SP_ST + k0+tq  ]);
                unsigned a2 = __float_as_uint(sP[(wm*16+g  )*SP_ST + k0+tq+4]);
                unsigned a3 = __float_as_uint(sP[(wm*16+g+8)*SP_ST + k0+tq+4]);
                #pragma unroll
                for (int j = 0; j < 4; j++) {
                    int n0 = wn*32 + (j << 3);
                    unsigned b0 = __float_as_uint(sE[(k0+tq  )*SE_ST + n0+g]);
                    unsigned b1 = __float_as_uint(sE[(k0+tq+4)*SE_ST + n0+g]);
                    mma_tf32(o[j], a0,a1,a2,a3, b0,b1);
                }
            }
        }
    }
    __syncthreads();

    // ---- epilogue: out = O / l ----
    {
        int r0 = wm*16 + g;
        int r1 = r0 + 8;
        float il0 = 1.0f / sL[r0];
        float il1 = 1.0f / sL[r1];
        #pragma unroll
        for (int j = 0; j < 4; j++) {
            int d0 = wn*32 + (j << 3) + 2*tq;
            size_t b0i = (size_t)(qt*QT + r0)*C_DIM + h*D_DIM + d0;
            size_t b1i = (size_t)(qt*QT + r1)*C_DIM + h*D_DIM + d0;
            out[b0i  ] = o[j][0]*il0;
            out[b0i+1] = o[j][1]*il0;
            out[b1i  ] = o[j][2]*il1;
            out[b1i+1] = o[j][3]*il1;
        }
    }
}

extern "C" void kernel_launch(void* const* d_in, const int* in_sizes, int n_in,
                              void* d_out, int out_size)
{
    (void)in_sizes; (void)n_in; (void)out_size;
    const float* x     = (const float*)d_in[0];
    const float* Wf    = (const float*)d_in[1];
    const float* bfn   = (const float*)d_in[2];
    const float* Wv    = (const float*)d_in[3];
    const float* temps = (const float*)d_in[4];
    const float* E     = (const float*)d_in[5];
    float* out = (float*)d_out;

    cudaFuncSetAttribute(vpf_kernel, cudaFuncAttributeMaxDynamicSharedMemorySize, SMEM_BYTES);
    dim3 grid(512/QT, 12);
    vpf_kernel<<<grid, 256, SMEM_BYTES>>>(x, Wf, bfn, Wv, temps, E, out);
}

// round 2
// speedup vs baseline: 3.4820x; 3.4820x over previous
#include <cuda_runtime.h>
#include <cstdint>

// VocabularyProjectionFFN as flash attention, round 2:
//  - KV-split x3 across blockIdx.z (grid 8x12x3 = 288 CTAs) + combine kernel
//  - intra-CTA split: 4 warp-pairs each own a 32-col slice of the 128-row KV tile
//  - softmax + P kept in registers (shuffle reductions + fragment permute)
//  - cp.async double-buffered K/E tile loads

#define QT 64
#define KT 128
#define D_DIM 64
#define V_SZ 32000
#define C_DIM 768
#define NSPLIT 3
#define TPS 84            // tiles per split (last split: 82)
#define NBLK 96           // h*8 + qt

#define SQ_ST 68
#define SK_ST 68
#define SE_ST 72

#define SK_OFF (QT*SQ_ST)                 // 4352
#define SE_OFF (SK_OFF + 2*KT*SK_ST)      // 21760
#define SMEM_FLOATS (SE_OFF + 2*KT*SE_ST) // 40192
#define SMEM_BYTES (SMEM_FLOATS*4)        // 160768

__device__ float g_Oscr[NSPLIT][NBLK][QT][D_DIM];
__device__ float g_Ms[NSPLIT][NBLK][QT];
__device__ float g_Ls[NSPLIT][NBLK][QT];

__device__ __forceinline__ float f2tf32(float x) {
    unsigned r;
    asm("cvt.rna.tf32.f32 %0, %1;" : "=r"(r) : "f"(x));
    return __uint_as_float(r);
}

__device__ __forceinline__ void mma_tf32(float* c,
    unsigned a0, unsigned a1, unsigned a2, unsigned a3,
    unsigned b0, unsigned b1)
{
    asm volatile(
        "mma.sync.aligned.m16n8k8.row.col.f32.tf32.tf32.f32 "
        "{%0,%1,%2,%3}, {%4,%5,%6,%7}, {%8,%9}, {%0,%1,%2,%3};"
        : "+f"(c[0]), "+f"(c[1]), "+f"(c[2]), "+f"(c[3])
        : "r"(a0), "r"(a1), "r"(a2), "r"(a3), "r"(b0), "r"(b1));
}

__device__ __forceinline__ void cpa16(uint32_t dst, const void* src) {
    asm volatile("cp.async.cg.shared.global [%0], [%1], 16;" :: "r"(dst), "l"(src));
}
__device__ __forceinline__ uint32_t s2u(const void* p) {
    return (uint32_t)__cvta_generic_to_shared(p);
}

extern "C" __global__ void __launch_bounds__(256)
vpf_main(const float* __restrict__ x,
         const float* __restrict__ Wf,
         const float* __restrict__ bfn,
         const float* __restrict__ Wv,
         const float* __restrict__ temps,
         const float* __restrict__ E)
{
    extern __shared__ float sm[];
    float* sQ = sm;                 // QT x SQ_ST
    float* sK = sm + SK_OFF;        // 2 stages x KT x SK_ST
    float* sE = sm + SE_OFF;        // 2 stages x KT x SE_ST

    const int qt  = blockIdx.x;
    const int h   = blockIdx.y;
    const int ks  = blockIdx.z;
    const int cb  = h*8 + qt;
    const int tid = threadIdx.x;
    const int warp = tid >> 5;
    const int lane = tid & 31;
    const int g  = lane >> 2;
    const int tq = lane & 3;
    const int pr = warp >> 1;       // pair 0..3 : KV cols [pr*32, pr*32+32)
    const int rq = warp & 1;        // row half  : rows [rq*32, rq*32+32)
    const int rbase = rq * 32;

    const float inv_temp = 1.0f / fmaxf(temps[h], 0.1f);

    // ---- Q prologue: X -> sK(stage0), W_ffn -> sE(stage0) ----
    for (int it = tid; it < QT*16; it += 256) {
        int i = it >> 4, c4 = (it & 15) << 2;
        *(float4*)(sK + i*SK_ST + c4) =
            *(const float4*)(x + (size_t)(qt*QT + i)*C_DIM + h*D_DIM + c4);
    }
    for (int it = tid; it < D_DIM*16; it += 256) {
        int e = it >> 4, c4 = (it & 15) << 2;
        *(float4*)(sE + e*SE_ST + c4) =
            *(const float4*)(Wf + ((size_t)h*D_DIM + e)*D_DIM + c4);
    }
    __syncthreads();
    {
        int i = tid >> 2, q = tid & 3;
        for (int j = 0; j < 16; j++) {
            int e = q + (j << 2);
            float acc = bfn[h*D_DIM + e];
            #pragma unroll
            for (int d = 0; d < D_DIM; d++)
                acc = fmaf(sK[i*SK_ST + d], sE[e*SE_ST + d], acc);
            sQ[i*SQ_ST + e] = f2tf32(acc * inv_temp);
        }
    }
    __syncthreads();   // sK/sE free for pipeline now

    // ---- per-warp state ----
    float o[2][8][4];
    #pragma unroll
    for (int mi = 0; mi < 2; mi++)
        #pragma unroll
        for (int n = 0; n < 8; n++)
            { o[mi][n][0]=0.f; o[mi][n][1]=0.f; o[mi][n][2]=0.f; o[mi][n][3]=0.f; }
    float st_m[4] = {-INFINITY,-INFINITY,-INFINITY,-INFINITY};
    float st_l[4] = {0.f,0.f,0.f,0.f};

    const int t_begin = ks * TPS;
    const int nt = (ks == 2) ? (V_SZ/KT - 2*TPS) : TPS;
    const float* Kg = Wv + (size_t)h * V_SZ * D_DIM;

    // stage issue: K tile (KT x 64) + E tile (KT x 64 slice)
    #define ISSUE(TG, S) do {                                                  \
        const float* kp_ = Kg + (size_t)(TG)*KT*D_DIM;                         \
        const float* ep_ = E + (size_t)(TG)*KT*C_DIM + h*D_DIM;                \
        float* dK_ = sK + (S)*KT*SK_ST;                                        \
        float* dE_ = sE + (S)*KT*SE_ST;                                        \
        for (int it = tid; it < KT*16; it += 256) {                            \
            int vi = it >> 4, c4 = (it & 15) << 2;                             \
            cpa16(s2u(dK_ + vi*SK_ST + c4), kp_ + (size_t)vi*D_DIM + c4);      \
        }                                                                      \
        for (int it = tid; it < KT*16; it += 256) {                            \
            int vi = it >> 4, c4 = (it & 15) << 2;                             \
            cpa16(s2u(dE_ + vi*SE_ST + c4), ep_ + (size_t)vi*C_DIM + c4);      \
        }                                                                      \
        asm volatile("cp.async.commit_group;" ::: "memory");                   \
    } while (0)

    ISSUE(t_begin, 0);

    for (int t = 0; t < nt; t++) {
        const int s = t & 1;
        asm volatile("cp.async.wait_group 0;" ::: "memory");
        __syncthreads();                          // tile t visible, prev compute done
        if (t + 1 < nt) ISSUE(t_begin + t + 1, s ^ 1);   // overlap with compute

        const float* cK = sK + s*KT*SK_ST;
        const float* cE = sE + s*KT*SE_ST;

        // ---- S = Q K^T : rows [rbase,rbase+32), cols [pr*32, pr*32+32) ----
        float sacc[2][4][4];
        #pragma unroll
        for (int mi = 0; mi < 2; mi++)
            #pragma unroll
            for (int j = 0; j < 4; j++)
                { sacc[mi][j][0]=0.f; sacc[mi][j][1]=0.f; sacc[mi][j][2]=0.f; sacc[mi][j][3]=0.f; }

        #pragma unroll
        for (int ki = 0; ki < 8; ki++) {
            int k0 = ki << 3;
            unsigned a[2][4];
            #pragma unroll
            for (int mi = 0; mi < 2; mi++) {
                int r = rbase + mi*16;
                a[mi][0] = __float_as_uint(sQ[(r+g  )*SQ_ST + k0+tq  ]);
                a[mi][1] = __float_as_uint(sQ[(r+g+8)*SQ_ST + k0+tq  ]);
                a[mi][2] = __float_as_uint(sQ[(r+g  )*SQ_ST + k0+tq+4]);
                a[mi][3] = __float_as_uint(sQ[(r+g+8)*SQ_ST + k0+tq+4]);
            }
            #pragma unroll
            for (int j = 0; j < 4; j++) {
                int n0 = pr*32 + (j << 3);
                unsigned b0 = __float_as_uint(cK[(n0+g)*SK_ST + k0+tq  ]);
                unsigned b1 = __float_as_uint(cK[(n0+g)*SK_ST + k0+tq+4]);
                mma_tf32(sacc[0][j], a[0][0],a[0][1],a[0][2],a[0][3], b0,b1);
                mma_tf32(sacc[1][j], a[1][0],a[1][1],a[1][2],a[1][3], b0,b1);
            }
        }

        // ---- online softmax, fully in registers ----
        float lm[4] = {-INFINITY,-INFINITY,-INFINITY,-INFINITY};
        #pragma unroll
        for (int mi = 0; mi < 2; mi++)
            #pragma unroll
            for (int j = 0; j < 4; j++) {
                lm[mi*2  ] = fmaxf(lm[mi*2  ], fmaxf(sacc[mi][j][0], sacc[mi][j][1]));
                lm[mi*2+1] = fmaxf(lm[mi*2+1], fmaxf(sacc[mi][j][2], sacc[mi][j][3]));
            }
        #pragma unroll
        for (int r = 0; r < 4; r++) {
            lm[r] = fmaxf(lm[r], __shfl_xor_sync(0xffffffffu, lm[r], 1));
            lm[r] = fmaxf(lm[r], __shfl_xor_sync(0xffffffffu, lm[r], 2));
        }
        float mnew[4], fac[4], lsum[4] = {0.f,0.f,0.f,0.f};
        #pragma unroll
        for (int r = 0; r < 4; r++) {
            mnew[r] = fmaxf(st_m[r], lm[r]);
            fac[r]  = __expf(st_m[r] - mnew[r]);
            st_m[r] = mnew[r];
        }
        #pragma unroll
        for (int mi = 0; mi < 2; mi++)
            #pragma unroll
            for (int j = 0; j < 4; j++) {
                float p0 = f2tf32(__expf(sacc[mi][j][0] - mnew[mi*2  ]));
                float p1 = f2tf32(__expf(sacc[mi][j][1] - mnew[mi*2  ]));
                float p2 = f2tf32(__expf(sacc[mi][j][2] - mnew[mi*2+1]));
                float p3 = f2tf32(__expf(sacc[mi][j][3] - mnew[mi*2+1]));
                sacc[mi][j][0]=p0; sacc[mi][j][1]=p1; sacc[mi][j][2]=p2; sacc[mi][j][3]=p3;
                lsum[mi*2  ] += p0 + p1;
                lsum[mi*2+1] += p2 + p3;
            }
        #pragma unroll
        for (int r = 0; r < 4; r++) {
            lsum[r] += __shfl_xor_sync(0xffffffffu, lsum[r], 1);
            lsum[r] += __shfl_xor_sync(0xffffffffu, lsum[r], 2);
            st_l[r] = st_l[r]*fac[r] + lsum[r];
        }
        #pragma unroll
        for (int mi = 0; mi < 2; mi++)
            #pragma unroll
            for (int n = 0; n < 8; n++) {
                o[mi][n][0] *= fac[mi*2  ]; o[mi][n][1] *= fac[mi*2  ];
                o[mi][n][2] *= fac[mi*2+1]; o[mi][n][3] *= fac[mi*2+1];
            }

        // ---- O += P @ E_slice : k = pair's 32 KV rows, N = 64 ----
        #pragma unroll
        for (int kf = 0; kf < 4; kf++) {
            // fragment permute: c-frag (cols 2tq,2tq+1) -> a-frag (cols tq,tq+4)
            unsigned A[2][4];
            int src = (lane & ~3) | (tq >> 1);
            #pragma unroll
            for (int mi = 0; mi < 2; mi++) {
                float x00 = __shfl_sync(0xffffffffu, sacc[mi][kf][0], src);
                float x01 = __shfl_sync(0xffffffffu, sacc[mi][kf][1], src);
                float y00 = __shfl_sync(0xffffffffu, sacc[mi][kf][0], src+2);
                float y01 = __shfl_sync(0xffffffffu, sacc[mi][kf][1], src+2);
                A[mi][0] = __float_as_uint((tq & 1) ? x01 : x00);
                A[mi][2] = __float_as_uint((tq & 1) ? y01 : y00);
                float x10 = __shfl_sync(0xffffffffu, sacc[mi][kf][2], src);
                float x11 = __shfl_sync(0xffffffffu, sacc[mi][kf][3], src);
                float y10 = __shfl_sync(0xffffffffu, sacc[mi][kf][2], src+2);
                float y11 = __shfl_sync(0xffffffffu, sacc[mi][kf][3], src+2);
                A[mi][1] = __float_as_uint((tq & 1) ? x11 : x10);
                A[mi][3] = __float_as_uint((tq & 1) ? y11 : y10);
            }
            int krow = pr*32 + (kf << 3);
            #pragma unroll
            for (int n = 0; n < 8; n++) {
                unsigned b0 = __float_as_uint(cE[(krow+tq  )*SE_ST + (n<<3)+g]);
                unsigned b1 = __float_as_uint(cE[(krow+tq+4)*SE_ST + (n<<3)+g]);
                mma_tf32(o[0][n], A[0][0],A[0][1],A[0][2],A[0][3], b0,b1);
                mma_tf32(o[1][n], A[1][0],A[1][1],A[1][2],A[1][3], b0,b1);
            }
        }
    }

    // ---- merge 4 pair-partials, write split-partial to scratch ----
    __syncthreads();
    float* mO = sK;             // [4][64][68]
    float* mM = sE;             // [4][64]
    float* mL = sE + 4*64;      // [4][64]
    float* fF = sE + 8*64;      // [4][64]

    #pragma unroll
    for (int mi = 0; mi < 2; mi++)
        #pragma unroll
        for (int n = 0; n < 8; n++) {
            int r0 = rbase + mi*16 + g, r1 = r0 + 8, c = (n<<3) + 2*tq;
            mO[(pr*64 + r0)*68 + c    ] = o[mi][n][0];
            mO[(pr*64 + r0)*68 + c + 1] = o[mi][n][1];
            mO[(pr*64 + r1)*68 + c    ] = o[mi][n][2];
            mO[(pr*64 + r1)*68 + c + 1] = o[mi][n][3];
        }
    if (tq == 0) {
        #pragma unroll
        for (int r = 0; r < 4; r++) {
            int row = rbase + (r >> 1)*16 + (r & 1)*8 + g;
            mM[pr*64 + row] = st_m[r];
            mL[pr*64 + row] = st_l[r];
        }
    }
    __syncthreads();
    if (tid < QT) {
        int row = tid;
        float M = mM[row];
        #pragma unroll
        for (int p = 1; p < 4; p++) M = fmaxf(M, mM[p*64 + row]);
        float L = 0.f;
        #pragma unroll
        for (int p = 0; p < 4; p++) {
            float f = __expf(mM[p*64 + row] - M);
            fF[p*64 + row] = f;
            L += mL[p*64 + row] * f;
        }
        g_Ms[ks][cb][row] = M;
        g_Ls[ks][cb][row] = L;
    }
    __syncthreads();
    for (int e = tid; e < QT*D_DIM; e += 256) {
        int row = e >> 6, d = e & 63;
        float sum = 0.f;
        #pragma unroll
        for (int p = 0; p < 4; p++)
            sum += mO[(p*64 + row)*68 + d] * fF[p*64 + row];
        g_Oscr[ks][cb][row][d] = sum;
    }
}

extern "C" __global__ void __launch_bounds__(256)
vpf_combine(float* __restrict__ out)
{
    const int cb = blockIdx.x;
    const int h = cb >> 3, qt = cb & 7;
    __shared__ float f[NSPLIT][QT];
    __shared__ float invL[QT];
    const int tid = threadIdx.x;

    if (tid < QT) {
        float M = -INFINITY;
        #pragma unroll
        for (int s = 0; s < NSPLIT; s++) M = fmaxf(M, g_Ms[s][cb][tid]);
        float L = 0.f;
        #pragma unroll
        for (int s = 0; s < NSPLIT; s++) {
            float e_ = __expf(g_Ms[s][cb][tid] - M);
            f[s][tid] = e_;
            L += g_Ls[s][cb][tid] * e_;
        }
        invL[tid] = 1.0f / L;
    }
    __syncthreads();
    for (int e = tid; e < QT*D_DIM; e += 256) {
        int row = e >> 6, d = e & 63;
        float s0 = 0.f;
        #pragma unroll
        for (int s = 0; s < NSPLIT; s++)
            s0 += g_Oscr[s][cb][row][d] * f[s][row];
        out[((size_t)(qt*QT + row))*C_DIM + h*D_DIM + d] = s0 * invL[row];
    }
}

extern "C" void kernel_launch(void* const* d_in, const int* in_sizes, int n_in,
                              void* d_out, int out_size)
{
    (void)in_sizes; (void)n_in; (void)out_size;
    const float* x     = (const float*)d_in[0];
    const float* Wf    = (const float*)d_in[1];
    const float* bfn   = (const float*)d_in[2];
    const float* Wv    = (const float*)d_in[3];
    const float* temps = (const float*)d_in[4];
    const float* E     = (const float*)d_in[5];
    float* out = (float*)d_out;

    cudaFuncSetAttribute(vpf_main, cudaFuncAttributeMaxDynamicSharedMemorySize, SMEM_BYTES);
    dim3 grid(8, 12, NSPLIT);
    vpf_main<<<grid, 256, SMEM_BYTES>>>(x, Wf, bfn, Wv, temps, E);
    vpf_combine<<<NBLK, 256>>>(out);
}